// round 1
// baseline (speedup 1.0000x reference)
#include <cuda_runtime.h>
#include <math.h>

#define D_DIM 1024
#define F_DIM 512
#define N_OUTG 8
#define E_TOT 16
#define T_MAX 1024
#define KT 16

// -------- scratch (no allocation allowed) --------
__device__ int   g_sel_ids[T_MAX * 3];
__device__ float g_sel_w[T_MAX * 3];
__device__ int   g_cnt[E_TOT];
__device__ int   g_list[E_TOT * T_MAX];          // packed (t<<2)|k
__device__ float g_H [T_MAX * 3 * F_DIM];        // 6.3 MB  : h = silu(g)*u per pair
__device__ float g_Ys[T_MAX * 3 * D_DIM];        // 12.6 MB : weighted down-proj per pair

// ======================= router =======================
// 24 dots per token: 0..7 outer gate, 8..23 inner gates (o*2+i).
__global__ void router_kernel(const float* __restrict__ x,
                              const float* __restrict__ w_out,
                              const float* __restrict__ w_in,
                              float* __restrict__ selw_out, int write_selw)
{
    int t = blockIdx.x;
    const float* xr = x + (size_t)t * D_DIM;
    int warp = threadIdx.x >> 5, lane = threadIdx.x & 31;
    __shared__ float s_dots[24];

    #pragma unroll
    for (int j = 0; j < 3; ++j) {
        int dix = warp * 3 + j;
        const float* wr = (dix < N_OUTG) ? (w_out + (size_t)dix * D_DIM)
                                         : (w_in  + (size_t)(dix - N_OUTG) * D_DIM);
        float acc = 0.f;
        for (int k = lane * 4; k < D_DIM; k += 128) {
            float4 a = *(const float4*)(xr + k);
            float4 b = *(const float4*)(wr + k);
            acc += a.x * b.x + a.y * b.y + a.z * b.z + a.w * b.w;
        }
        #pragma unroll
        for (int off = 16; off > 0; off >>= 1)
            acc += __shfl_xor_sync(0xffffffffu, acc, off);
        if (lane == 0) s_dots[dix] = acc;
    }
    __syncthreads();

    if (threadIdx.x == 0) {
        float l[N_OUTG];
        #pragma unroll
        for (int i = 0; i < N_OUTG; ++i) l[i] = s_dots[i];
        // top-2 on logits == top-2 on softmax probs; ties -> lower index
        int a1 = 0;
        #pragma unroll
        for (int i = 1; i < N_OUTG; ++i) if (l[i] > l[a1]) a1 = i;
        int a2 = (a1 == 0) ? 1 : 0;
        #pragma unroll
        for (int i = 0; i < N_OUTG; ++i) if (i != a1 && l[i] > l[a2]) a2 = i;
        // normalized top-2 softmax weights (exact-math equal to reference)
        float e2 = expf(l[a2] - l[a1]);
        float w0 = 1.f / (1.f + e2);
        float w1 = e2 / (1.f + e2);

        // inner top-k per pattern (2,1); jax top_k ties keep lower index
        float sA0 = s_dots[8 + a1 * 2], sA1 = s_dots[8 + a1 * 2 + 1];
        int i0 = (sA1 > sA0) ? 1 : 0;
        float sB0 = s_dots[8 + a2 * 2], sB1 = s_dots[8 + a2 * 2 + 1];
        int i2 = (sB1 > sB0) ? 1 : 0;

        int   ids[3] = { a1 * 2 + i0, a1 * 2 + (1 - i0), a2 * 2 + i2 };
        float ws [3] = { w0, w0, w1 };
        #pragma unroll
        for (int k = 0; k < 3; ++k) {
            g_sel_ids[t * 3 + k] = ids[k];
            g_sel_w  [t * 3 + k] = ws[k];
            if (write_selw) selw_out[t * 3 + k] = ws[k];
        }
    }
}

// ======================= grouping =======================
__global__ void zero_cnt_kernel() {
    if (threadIdx.x < E_TOT) g_cnt[threadIdx.x] = 0;
}

__global__ void group_kernel(int T) {
    int p = blockIdx.x * blockDim.x + threadIdx.x;
    if (p < 3 * T) {
        int t = p / 3, k = p - 3 * t;
        int e = g_sel_ids[p];
        int pos = atomicAdd(&g_cnt[e], 1);
        g_list[e * T_MAX + pos] = (t << 2) | k;
    }
}

// ======================= gate+up GEMM (fused SwiGLU) =======================
// Block: 64 tokens x 64 f, computes G and U simultaneously (X tile reused).
__global__ __launch_bounds__(256, 2)
void gateup_kernel(const float* __restrict__ x,
                   const float* __restrict__ wg,
                   const float* __restrict__ wu)
{
    int e  = blockIdx.y;
    int n  = g_cnt[e];
    int t0 = blockIdx.z * 64;
    if (t0 >= n) return;
    int f0 = blockIdx.x * 64;

    __shared__ float Xs[KT][64];
    __shared__ float Gs[KT][64];
    __shared__ float Us[KT][64];

    int tid = threadIdx.x;
    int r = tid >> 2;       // 0..63: load row (token row for Xs, f row for Gs/Us)
    int q = tid & 3;        // k quad within the 16-wide k tile
    int tx = tid & 15;      // f micro-tile
    int ty = tid >> 4;      // token micro-tile

    int rowt = t0 + r;
    int pr = (rowt < n) ? g_list[e * T_MAX + rowt] : -1;
    const float* xrow = (pr >= 0) ? (x + (size_t)(pr >> 2) * D_DIM) : x;
    const float* wgE = wg + ((size_t)e * F_DIM + f0 + r) * D_DIM;
    const float* wuE = wu + ((size_t)e * F_DIM + f0 + r) * D_DIM;

    float accG[4][4] = {}, accU[4][4] = {};

    float4 pX = (pr >= 0) ? *(const float4*)(xrow + q * 4) : make_float4(0, 0, 0, 0);
    float4 pG = *(const float4*)(wgE + q * 4);
    float4 pU = *(const float4*)(wuE + q * 4);

    for (int k0 = 0; k0 < D_DIM; k0 += KT) {
        Xs[q*4+0][r] = pX.x; Xs[q*4+1][r] = pX.y; Xs[q*4+2][r] = pX.z; Xs[q*4+3][r] = pX.w;
        Gs[q*4+0][r] = pG.x; Gs[q*4+1][r] = pG.y; Gs[q*4+2][r] = pG.z; Gs[q*4+3][r] = pG.w;
        Us[q*4+0][r] = pU.x; Us[q*4+1][r] = pU.y; Us[q*4+2][r] = pU.z; Us[q*4+3][r] = pU.w;
        __syncthreads();

        int kn = k0 + KT;
        if (kn < D_DIM) {   // prefetch next stage; LDG latency overlaps compute
            pX = (pr >= 0) ? *(const float4*)(xrow + kn + q * 4) : make_float4(0, 0, 0, 0);
            pG = *(const float4*)(wgE + kn + q * 4);
            pU = *(const float4*)(wuE + kn + q * 4);
        }

        #pragma unroll
        for (int kk = 0; kk < KT; ++kk) {
            float4 a  = *(const float4*)&Xs[kk][ty * 4];
            float4 bg = *(const float4*)&Gs[kk][tx * 4];
            float4 bu = *(const float4*)&Us[kk][tx * 4];
            float av[4]  = { a.x,  a.y,  a.z,  a.w };
            float bgv[4] = { bg.x, bg.y, bg.z, bg.w };
            float buv[4] = { bu.x, bu.y, bu.z, bu.w };
            #pragma unroll
            for (int i = 0; i < 4; ++i)
                #pragma unroll
                for (int j = 0; j < 4; ++j) {
                    accG[i][j] += av[i] * bgv[j];
                    accU[i][j] += av[i] * buv[j];
                }
        }
        __syncthreads();
    }

    // epilogue: h = silu(g) * u, scattered to pair rows
    #pragma unroll
    for (int i = 0; i < 4; ++i) {
        int rowt2 = t0 + ty * 4 + i;
        if (rowt2 < n) {
            int pr2 = g_list[e * T_MAX + rowt2];
            int prow = (pr2 >> 2) * 3 + (pr2 & 3);
            float h[4];
            #pragma unroll
            for (int j = 0; j < 4; ++j) {
                float g = accG[i][j], u = accU[i][j];
                float sig = 1.f / (1.f + expf(-g));
                h[j] = g * sig * u;
            }
            *(float4*)(g_H + (size_t)prow * F_DIM + f0 + tx * 4)
                = make_float4(h[0], h[1], h[2], h[3]);
        }
    }
}

// ======================= down GEMM (weighted) =======================
__global__ __launch_bounds__(256, 2)
void down_kernel(const float* __restrict__ wd)
{
    int e  = blockIdx.y;
    int n  = g_cnt[e];
    int t0 = blockIdx.z * 64;
    if (t0 >= n) return;
    int d0 = blockIdx.x * 64;

    __shared__ float Hs[KT][64];
    __shared__ float Ws[KT][64];

    int tid = threadIdx.x;
    int r = tid >> 2, q = tid & 3;
    int tx = tid & 15, ty = tid >> 4;

    int rowt = t0 + r;
    int pr = (rowt < n) ? g_list[e * T_MAX + rowt] : -1;
    const float* hrow = (pr >= 0)
        ? (g_H + (size_t)((pr >> 2) * 3 + (pr & 3)) * F_DIM) : g_H;
    const float* wdE = wd + ((size_t)e * D_DIM + d0 + r) * F_DIM;

    float acc[4][4] = {};

    float4 pH = (pr >= 0) ? *(const float4*)(hrow + q * 4) : make_float4(0, 0, 0, 0);
    float4 pW = *(const float4*)(wdE + q * 4);

    for (int k0 = 0; k0 < F_DIM; k0 += KT) {
        Hs[q*4+0][r] = pH.x; Hs[q*4+1][r] = pH.y; Hs[q*4+2][r] = pH.z; Hs[q*4+3][r] = pH.w;
        Ws[q*4+0][r] = pW.x; Ws[q*4+1][r] = pW.y; Ws[q*4+2][r] = pW.z; Ws[q*4+3][r] = pW.w;
        __syncthreads();

        int kn = k0 + KT;
        if (kn < F_DIM) {
            pH = (pr >= 0) ? *(const float4*)(hrow + kn + q * 4) : make_float4(0, 0, 0, 0);
            pW = *(const float4*)(wdE + kn + q * 4);
        }

        #pragma unroll
        for (int kk = 0; kk < KT; ++kk) {
            float4 a = *(const float4*)&Hs[kk][ty * 4];
            float4 b = *(const float4*)&Ws[kk][tx * 4];
            float av[4] = { a.x, a.y, a.z, a.w };
            float bv[4] = { b.x, b.y, b.z, b.w };
            #pragma unroll
            for (int i = 0; i < 4; ++i)
                #pragma unroll
                for (int j = 0; j < 4; ++j)
                    acc[i][j] += av[i] * bv[j];
        }
        __syncthreads();
    }

    #pragma unroll
    for (int i = 0; i < 4; ++i) {
        int rowt2 = t0 + ty * 4 + i;
        if (rowt2 < n) {
            int pr2 = g_list[e * T_MAX + rowt2];
            int prow = (pr2 >> 2) * 3 + (pr2 & 3);
            float wsel = g_sel_w[prow];
            *(float4*)(g_Ys + (size_t)prow * D_DIM + d0 + tx * 4)
                = make_float4(acc[i][0] * wsel, acc[i][1] * wsel,
                              acc[i][2] * wsel, acc[i][3] * wsel);
        }
    }
}

// ======================= deterministic combine =======================
__global__ void combine_kernel(float* __restrict__ out, int T)
{
    int gid = blockIdx.x * blockDim.x + threadIdx.x;
    int total = T * (D_DIM / 4);
    if (gid < total) {
        int t  = gid / (D_DIM / 4);
        int dq = gid - t * (D_DIM / 4);
        const float4* y0 = (const float4*)(g_Ys + (size_t)(t * 3 + 0) * D_DIM) + dq;
        const float4* y1 = (const float4*)(g_Ys + (size_t)(t * 3 + 1) * D_DIM) + dq;
        const float4* y2 = (const float4*)(g_Ys + (size_t)(t * 3 + 2) * D_DIM) + dq;
        float4 a = *y0, b = *y1, c = *y2;
        ((float4*)out)[gid] = make_float4(a.x + b.x + c.x, a.y + b.y + c.y,
                                          a.z + b.z + c.z, a.w + b.w + c.w);
    }
}

// ======================= launch =======================
extern "C" void kernel_launch(void* const* d_in, const int* in_sizes, int n_in,
                              void* d_out, int out_size)
{
    const float* x     = (const float*)d_in[0];
    const float* w_out = (const float*)d_in[1];
    const float* w_in  = (const float*)d_in[2];
    const float* wg    = (const float*)d_in[3];
    const float* wu    = (const float*)d_in[4];
    const float* wd    = (const float*)d_in[5];
    float* out = (float*)d_out;

    int T = in_sizes[0] / D_DIM;
    if (T > T_MAX) T = T_MAX;
    int write_selw = (out_size >= T * D_DIM + 3 * T) ? 1 : 0;

    router_kernel<<<T, 256>>>(x, w_out, w_in, out + (size_t)T * D_DIM, write_selw);
    zero_cnt_kernel<<<1, 32>>>();
    group_kernel<<<(3 * T + 255) / 256, 256>>>(T);

    int ttiles = (T + 63) / 64;
    dim3 g1(F_DIM / 64, E_TOT, ttiles);
    gateup_kernel<<<g1, 256>>>(x, wg, wu);
    dim3 g2(D_DIM / 64, E_TOT, ttiles);
    down_kernel<<<g2, 256>>>(wd);

    combine_kernel<<<(T * (D_DIM / 4) + 255) / 256, 256>>>(out, T);
}

// round 2
// speedup vs baseline: 3.2704x; 3.2704x over previous
#include <cuda_runtime.h>
#include <math.h>

#define D_DIM 1024
#define F_DIM 512
#define N_OUTG 8
#define E_TOT 16
#define T_MAX 1024

#define BM 64
#define BN 64
#define BK 32
#define AS 36   // smem row stride (words), padded: conflict-free frag loads

// -------- scratch (no allocation allowed) --------
__device__ int   g_sel_ids[T_MAX * 3];
__device__ float g_sel_w[T_MAX * 3];
__device__ int   g_cnt[E_TOT];
__device__ int   g_list[E_TOT * T_MAX];          // packed (t<<2)|k
__device__ float g_H [T_MAX * 3 * F_DIM];        // h = silu(g)*u per pair
__device__ float g_Ys[T_MAX * 3 * D_DIM];        // weighted down-proj per pair

// ---------------- tf32 helpers ----------------
__device__ __forceinline__ unsigned f2tf(float f) {
    unsigned u;
    asm("cvt.rna.tf32.f32 %0, %1;" : "=r"(u) : "f"(f));
    return u;
}
__device__ __forceinline__ uint4 cvt4(float4 v) {
    uint4 r; r.x = f2tf(v.x); r.y = f2tf(v.y); r.z = f2tf(v.z); r.w = f2tf(v.w);
    return r;
}
__device__ __forceinline__ void mma_tf32(float* c, const unsigned* a,
                                         unsigned b0, unsigned b1) {
    asm volatile(
        "mma.sync.aligned.m16n8k8.row.col.f32.tf32.tf32.f32 "
        "{%0,%1,%2,%3}, {%4,%5,%6,%7}, {%8,%9}, {%0,%1,%2,%3};\n"
        : "+f"(c[0]), "+f"(c[1]), "+f"(c[2]), "+f"(c[3])
        : "r"(a[0]), "r"(a[1]), "r"(a[2]), "r"(a[3]), "r"(b0), "r"(b1));
}

// ======================= router (exact fp32) =======================
__global__ void router_kernel(const float* __restrict__ x,
                              const float* __restrict__ w_out,
                              const float* __restrict__ w_in,
                              float* __restrict__ selw_out, int write_selw)
{
    int t = blockIdx.x;
    const float* xr = x + (size_t)t * D_DIM;
    int warp = threadIdx.x >> 5, lane = threadIdx.x & 31;
    __shared__ float s_dots[24];

    #pragma unroll
    for (int j = 0; j < 3; ++j) {
        int dix = warp * 3 + j;
        const float* wr = (dix < N_OUTG) ? (w_out + (size_t)dix * D_DIM)
                                         : (w_in  + (size_t)(dix - N_OUTG) * D_DIM);
        float acc = 0.f;
        for (int k = lane * 4; k < D_DIM; k += 128) {
            float4 a = *(const float4*)(xr + k);
            float4 b = *(const float4*)(wr + k);
            acc += a.x * b.x + a.y * b.y + a.z * b.z + a.w * b.w;
        }
        #pragma unroll
        for (int off = 16; off > 0; off >>= 1)
            acc += __shfl_xor_sync(0xffffffffu, acc, off);
        if (lane == 0) s_dots[dix] = acc;
    }
    __syncthreads();

    if (threadIdx.x == 0) {
        float l[N_OUTG];
        #pragma unroll
        for (int i = 0; i < N_OUTG; ++i) l[i] = s_dots[i];
        int a1 = 0;
        #pragma unroll
        for (int i = 1; i < N_OUTG; ++i) if (l[i] > l[a1]) a1 = i;
        int a2 = (a1 == 0) ? 1 : 0;
        #pragma unroll
        for (int i = 0; i < N_OUTG; ++i) if (i != a1 && l[i] > l[a2]) a2 = i;
        float e2 = expf(l[a2] - l[a1]);
        float w0 = 1.f / (1.f + e2);
        float w1 = e2 / (1.f + e2);

        float sA0 = s_dots[8 + a1 * 2], sA1 = s_dots[8 + a1 * 2 + 1];
        int i0 = (sA1 > sA0) ? 1 : 0;
        float sB0 = s_dots[8 + a2 * 2], sB1 = s_dots[8 + a2 * 2 + 1];
        int i2 = (sB1 > sB0) ? 1 : 0;

        int   ids[3] = { a1 * 2 + i0, a1 * 2 + (1 - i0), a2 * 2 + i2 };
        float ws [3] = { w0, w0, w1 };
        #pragma unroll
        for (int k = 0; k < 3; ++k) {
            g_sel_ids[t * 3 + k] = ids[k];
            g_sel_w  [t * 3 + k] = ws[k];
            if (write_selw) selw_out[t * 3 + k] = ws[k];
        }
    }
}

// ======================= grouping =======================
__global__ void zero_cnt_kernel() {
    if (threadIdx.x < E_TOT) g_cnt[threadIdx.x] = 0;
}
__global__ void group_kernel(int T) {
    int p = blockIdx.x * blockDim.x + threadIdx.x;
    if (p < 3 * T) {
        int t = p / 3, k = p - 3 * t;
        int e = g_sel_ids[p];
        int pos = atomicAdd(&g_cnt[e], 1);
        g_list[e * T_MAX + pos] = (t << 2) | k;
    }
}

// ======================= gate+up GEMM (tf32 MMA, fused SwiGLU) =======================
// 64 tokens x 64 f per CTA, 128 threads = 2x2 warps, warp tile 32x32.
__global__ __launch_bounds__(128)
void gateup_kernel(const float* __restrict__ x,
                   const float* __restrict__ wg,
                   const float* __restrict__ wu)
{
    int e  = blockIdx.y;
    int n  = g_cnt[e];
    int t0 = blockIdx.z * BM;
    if (t0 >= n) return;
    int f0 = blockIdx.x * BN;

    __shared__ unsigned As[BM * AS];
    __shared__ unsigned Gs[BN * AS];
    __shared__ unsigned Us[BN * AS];
    __shared__ int s_pr[BM];

    int tid  = threadIdx.x;
    int warp = tid >> 5, lane = tid & 31;
    int wm = warp >> 1, wn = warp & 1;
    int g  = lane >> 2, t4 = lane & 3;

    if (tid < BM) {
        int rowt = t0 + tid;
        s_pr[tid] = (rowt < n) ? g_list[e * T_MAX + rowt] : -1;
    }
    __syncthreads();

    // global load mapping: thread covers rows {i*16+mi}, k-quad kq
    int mi = tid >> 3, kq = tid & 7;
    const float* wgp = wg + ((size_t)e * F_DIM + f0 + mi) * D_DIM + kq * 4;
    const float* wup = wu + ((size_t)e * F_DIM + f0 + mi) * D_DIM + kq * 4;
    size_t aoff[4];
    #pragma unroll
    for (int i = 0; i < 4; ++i) {
        int pr = s_pr[i * 16 + mi];
        aoff[i] = (size_t)((pr < 0) ? 0 : (pr >> 2)) * D_DIM + kq * 4;
    }

    float4 ra[4], rg[4], ru[4];
    #pragma unroll
    for (int i = 0; i < 4; ++i) {
        ra[i] = *(const float4*)(x + aoff[i]);
        rg[i] = *(const float4*)(wgp + (size_t)i * 16 * D_DIM);
        ru[i] = *(const float4*)(wup + (size_t)i * 16 * D_DIM);
    }

    float accG[2][4][4] = {}, accU[2][4][4] = {};

    for (int k0 = 0; k0 < D_DIM; k0 += BK) {
        #pragma unroll
        for (int i = 0; i < 4; ++i) {
            int m = i * 16 + mi;
            *(uint4*)(As + m * AS + kq * 4) = cvt4(ra[i]);
            *(uint4*)(Gs + m * AS + kq * 4) = cvt4(rg[i]);
            *(uint4*)(Us + m * AS + kq * 4) = cvt4(ru[i]);
        }
        __syncthreads();

        int kn = k0 + BK;
        if (kn < D_DIM) {
            #pragma unroll
            for (int i = 0; i < 4; ++i) {
                ra[i] = *(const float4*)(x + aoff[i] + kn);
                rg[i] = *(const float4*)(wgp + kn + (size_t)i * 16 * D_DIM);
                ru[i] = *(const float4*)(wup + kn + (size_t)i * 16 * D_DIM);
            }
        }

        #pragma unroll
        for (int ks = 0; ks < 4; ++ks) {
            unsigned a[2][4];
            #pragma unroll
            for (int mf = 0; mf < 2; ++mf) {
                int mb = wm * 32 + mf * 16;
                a[mf][0] = As[(mb + g    ) * AS + ks * 8 + t4    ];
                a[mf][1] = As[(mb + g + 8) * AS + ks * 8 + t4    ];
                a[mf][2] = As[(mb + g    ) * AS + ks * 8 + t4 + 4];
                a[mf][3] = As[(mb + g + 8) * AS + ks * 8 + t4 + 4];
            }
            #pragma unroll
            for (int nf = 0; nf < 4; ++nf) {
                int nb = wn * 32 + nf * 8;
                unsigned b0 = Gs[(nb + g) * AS + ks * 8 + t4    ];
                unsigned b1 = Gs[(nb + g) * AS + ks * 8 + t4 + 4];
                mma_tf32(accG[0][nf], a[0], b0, b1);
                mma_tf32(accG[1][nf], a[1], b0, b1);
                unsigned u0 = Us[(nb + g) * AS + ks * 8 + t4    ];
                unsigned u1 = Us[(nb + g) * AS + ks * 8 + t4 + 4];
                mma_tf32(accU[0][nf], a[0], u0, u1);
                mma_tf32(accU[1][nf], a[1], u0, u1);
            }
        }
        __syncthreads();
    }

    // epilogue: h = silu(g)*u scattered to pair rows
    #pragma unroll
    for (int mf = 0; mf < 2; ++mf) {
        #pragma unroll
        for (int h = 0; h < 2; ++h) {
            int m = wm * 32 + mf * 16 + g + h * 8;
            int rowt = t0 + m;
            if (rowt < n) {
                int pr = s_pr[m];
                int prow = (pr >> 2) * 3 + (pr & 3);
                float* Hrow = g_H + (size_t)prow * F_DIM + f0;
                #pragma unroll
                for (int nf = 0; nf < 4; ++nf) {
                    float gv0 = accG[mf][nf][h * 2], gv1 = accG[mf][nf][h * 2 + 1];
                    float uv0 = accU[mf][nf][h * 2], uv1 = accU[mf][nf][h * 2 + 1];
                    float h0 = gv0 / (1.f + expf(-gv0)) * uv0;
                    float h1 = gv1 / (1.f + expf(-gv1)) * uv1;
                    *(float2*)(Hrow + wn * 32 + nf * 8 + t4 * 2) = make_float2(h0, h1);
                }
            }
        }
    }
}

// ======================= down GEMM (tf32 MMA, weighted) =======================
__global__ __launch_bounds__(128)
void down_kernel(const float* __restrict__ wd)
{
    int e  = blockIdx.y;
    int n  = g_cnt[e];
    int t0 = blockIdx.z * BM;
    if (t0 >= n) return;
    int d0 = blockIdx.x * BN;

    __shared__ unsigned Hs[BM * AS];
    __shared__ unsigned Ws[BN * AS];
    __shared__ int s_pr[BM];

    int tid  = threadIdx.x;
    int warp = tid >> 5, lane = tid & 31;
    int wm = warp >> 1, wn = warp & 1;
    int g  = lane >> 2, t4 = lane & 3;

    if (tid < BM) {
        int rowt = t0 + tid;
        s_pr[tid] = (rowt < n) ? g_list[e * T_MAX + rowt] : -1;
    }
    __syncthreads();

    int mi = tid >> 3, kq = tid & 7;
    const float* wdp = wd + ((size_t)e * D_DIM + d0 + mi) * F_DIM + kq * 4;
    size_t hoff[4];
    #pragma unroll
    for (int i = 0; i < 4; ++i) {
        int pr = s_pr[i * 16 + mi];
        int prow = (pr < 0) ? 0 : ((pr >> 2) * 3 + (pr & 3));
        hoff[i] = (size_t)prow * F_DIM + kq * 4;
    }

    float4 rh[4], rw[4];
    #pragma unroll
    for (int i = 0; i < 4; ++i) {
        rh[i] = *(const float4*)(g_H + hoff[i]);
        rw[i] = *(const float4*)(wdp + (size_t)i * 16 * F_DIM);
    }

    float acc[2][4][4] = {};

    for (int k0 = 0; k0 < F_DIM; k0 += BK) {
        #pragma unroll
        for (int i = 0; i < 4; ++i) {
            int m = i * 16 + mi;
            *(uint4*)(Hs + m * AS + kq * 4) = cvt4(rh[i]);
            *(uint4*)(Ws + m * AS + kq * 4) = cvt4(rw[i]);
        }
        __syncthreads();

        int kn = k0 + BK;
        if (kn < F_DIM) {
            #pragma unroll
            for (int i = 0; i < 4; ++i) {
                rh[i] = *(const float4*)(g_H + hoff[i] + kn);
                rw[i] = *(const float4*)(wdp + kn + (size_t)i * 16 * F_DIM);
            }
        }

        #pragma unroll
        for (int ks = 0; ks < 4; ++ks) {
            unsigned a[2][4];
            #pragma unroll
            for (int mf = 0; mf < 2; ++mf) {
                int mb = wm * 32 + mf * 16;
                a[mf][0] = Hs[(mb + g    ) * AS + ks * 8 + t4    ];
                a[mf][1] = Hs[(mb + g + 8) * AS + ks * 8 + t4    ];
                a[mf][2] = Hs[(mb + g    ) * AS + ks * 8 + t4 + 4];
                a[mf][3] = Hs[(mb + g + 8) * AS + ks * 8 + t4 + 4];
            }
            #pragma unroll
            for (int nf = 0; nf < 4; ++nf) {
                int nb = wn * 32 + nf * 8;
                unsigned b0 = Ws[(nb + g) * AS + ks * 8 + t4    ];
                unsigned b1 = Ws[(nb + g) * AS + ks * 8 + t4 + 4];
                mma_tf32(acc[0][nf], a[0], b0, b1);
                mma_tf32(acc[1][nf], a[1], b0, b1);
            }
        }
        __syncthreads();
    }

    #pragma unroll
    for (int mf = 0; mf < 2; ++mf) {
        #pragma unroll
        for (int h = 0; h < 2; ++h) {
            int m = wm * 32 + mf * 16 + g + h * 8;
            int rowt = t0 + m;
            if (rowt < n) {
                int pr = s_pr[m];
                int prow = (pr >> 2) * 3 + (pr & 3);
                float wsel = g_sel_w[prow];
                float* Yrow = g_Ys + (size_t)prow * D_DIM + d0;
                #pragma unroll
                for (int nf = 0; nf < 4; ++nf) {
                    float y0 = acc[mf][nf][h * 2] * wsel;
                    float y1 = acc[mf][nf][h * 2 + 1] * wsel;
                    *(float2*)(Yrow + wn * 32 + nf * 8 + t4 * 2) = make_float2(y0, y1);
                }
            }
        }
    }
}

// ======================= deterministic combine =======================
__global__ void combine_kernel(float* __restrict__ out, int T)
{
    int gid = blockIdx.x * blockDim.x + threadIdx.x;
    int total = T * (D_DIM / 4);
    if (gid < total) {
        int t  = gid / (D_DIM / 4);
        int dq = gid - t * (D_DIM / 4);
        const float4* y0 = (const float4*)(g_Ys + (size_t)(t * 3 + 0) * D_DIM) + dq;
        const float4* y1 = (const float4*)(g_Ys + (size_t)(t * 3 + 1) * D_DIM) + dq;
        const float4* y2 = (const float4*)(g_Ys + (size_t)(t * 3 + 2) * D_DIM) + dq;
        float4 a = *y0, b = *y1, c = *y2;
        ((float4*)out)[gid] = make_float4(a.x + b.x + c.x, a.y + b.y + c.y,
                                          a.z + b.z + c.z, a.w + b.w + c.w);
    }
}

// ======================= launch =======================
extern "C" void kernel_launch(void* const* d_in, const int* in_sizes, int n_in,
                              void* d_out, int out_size)
{
    const float* x     = (const float*)d_in[0];
    const float* w_out = (const float*)d_in[1];
    const float* w_in  = (const float*)d_in[2];
    const float* wg    = (const float*)d_in[3];
    const float* wu    = (const float*)d_in[4];
    const float* wd    = (const float*)d_in[5];
    float* out = (float*)d_out;

    int T = in_sizes[0] / D_DIM;
    if (T > T_MAX) T = T_MAX;
    int write_selw = (out_size >= T * D_DIM + 3 * T) ? 1 : 0;

    router_kernel<<<T, 256>>>(x, w_out, w_in, out + (size_t)T * D_DIM, write_selw);
    zero_cnt_kernel<<<1, 32>>>();
    group_kernel<<<(3 * T + 255) / 256, 256>>>(T);

    int ttiles = (T + BM - 1) / BM;
    dim3 g1(F_DIM / BN, E_TOT, ttiles);
    gateup_kernel<<<g1, 128>>>(x, wg, wu);
    dim3 g2(D_DIM / BN, E_TOT, ttiles);
    down_kernel<<<g2, 128>>>(wd);

    combine_kernel<<<(T * (D_DIM / 4) + 255) / 256, 256>>>(out, T);
}